// round 1
// baseline (speedup 1.0000x reference)
#include <cuda_runtime.h>
#include <cuda_bf16.h>

#define N_PTS 100000
#define C_IN 24
#define C_HID 144
#define C_OUT 24
#define KS 9
#define EPS 1e-5f

// ---- scratch (device globals: allocation-free rule) ----
__device__ float g_x1[N_PTS * C_HID];   // GEMM1 output (pre-BN)
__device__ float g_x2[N_PTS * C_HID];   // conv output (pre-BN)
__device__ float g_y [N_PTS * C_OUT];   // GEMM3 output (pre-BN)

__device__ float g_s1[C_HID], g_q1[C_HID];
__device__ float g_s2[C_HID], g_q2[C_HID];
__device__ float g_s3[C_OUT], g_q3[C_OUT];
__device__ float g_scale1[C_HID], g_shift1[C_HID];
__device__ float g_scale2[C_HID], g_shift2[C_HID];
__device__ float g_scale3[C_OUT], g_shift3[C_OUT];

// ---- K0: zero the stat accumulators (graph replays must be deterministic) ----
__global__ void k0_zero() {
    int i = threadIdx.x;
    if (i < C_HID) {
        g_s1[i] = 0.f; g_q1[i] = 0.f;
        g_s2[i] = 0.f; g_q2[i] = 0.f;
    }
    if (i < C_OUT) { g_s3[i] = 0.f; g_q3[i] = 0.f; }
}

// ---- K1: x1 = feats @ w1, accumulate per-channel sum/sumsq ----
#define ROWS1 64
__global__ void k1_gemm1(const float* __restrict__ feats,
                         const float* __restrict__ w1) {
    __shared__ float sf[ROWS1][C_IN];
    int c = threadIdx.x;               // 0..143, one output channel per thread
    int row0 = blockIdx.x * ROWS1;
    int nrows = min(ROWS1, N_PTS - row0);

    for (int i = threadIdx.x; i < nrows * C_IN; i += blockDim.x)
        sf[i / C_IN][i % C_IN] = feats[row0 * C_IN + i];
    __syncthreads();

    float wcol[C_IN];
#pragma unroll
    for (int k = 0; k < C_IN; k++) wcol[k] = w1[k * C_HID + c];

    float s = 0.f, q = 0.f;
    for (int r = 0; r < nrows; r++) {
        float acc = 0.f;
#pragma unroll
        for (int k = 0; k < C_IN; k++) acc += sf[r][k] * wcol[k];
        g_x1[(row0 + r) * C_HID + c] = acc;
        s += acc; q += acc * acc;
    }
    atomicAdd(&g_s1[c], s);
    atomicAdd(&g_q1[c], q);
}

// ---- finalize BN: bn(x) = x*scale + shift ----
__global__ void k_fin(const float* __restrict__ g, const float* __restrict__ b,
                      const float* __restrict__ sum, const float* __restrict__ sq,
                      float* __restrict__ scale, float* __restrict__ shift, int C) {
    int c = threadIdx.x;
    if (c < C) {
        float m = sum[c] * (1.0f / N_PTS);
        float v = sq[c] * (1.0f / N_PTS) - m * m;
        float sc = g[c] * rsqrtf(v + EPS);
        scale[c] = sc;
        shift[c] = b[c] - m * sc;
    }
}

// ---- K3: channelwise 3x3 sparse conv (gather form) + BN2 stats ----
// out[p,c] = sum_k w2[k,c] * relu6(bn1(x1[nbr_k(p), c])), nbr from in_idx.
#define ROWS3 16
__global__ void k3_conv(const float* __restrict__ w2,
                        const int* __restrict__ in_idx) {
    __shared__ int snbr[ROWS3][KS];
    int c = threadIdx.x;               // 0..143
    int row0 = blockIdx.x * ROWS3;
    int nrows = min(ROWS3, N_PTS - row0);

    for (int i = threadIdx.x; i < nrows * KS; i += blockDim.x) {
        int r = i / KS, k = i % KS;
        snbr[r][k] = in_idx[k * N_PTS + row0 + r];
    }
    __syncthreads();

    float wk[KS];
#pragma unroll
    for (int k = 0; k < KS; k++) wk[k] = w2[k * C_HID + c];
    float sc = g_scale1[c], sh = g_shift1[c];

    float s = 0.f, q = 0.f;
    for (int r = 0; r < nrows; r++) {
        float acc = 0.f;
#pragma unroll
        for (int k = 0; k < KS; k++) {
            int nbr = snbr[r][k];
            if (nbr < N_PTS) {
                float x = g_x1[nbr * C_HID + c];
                x = fminf(fmaxf(x * sc + sh, 0.f), 6.f);
                acc += wk[k] * x;
            }
        }
        g_x2[(row0 + r) * C_HID + c] = acc;
        s += acc; q += acc * acc;
    }
    atomicAdd(&g_s2[c], s);
    atomicAdd(&g_q2[c], q);
}

// ---- K5: y = relu6(bn2(x2)) @ w3 + BN3 stats ----
#define ROWS5 32
#define T5 192   // 24 cols x 8 row-lanes
__global__ void k5_gemm3(const float* __restrict__ w3) {
    __shared__ float sx[ROWS5][C_HID + 1];
    __shared__ float sw[C_HID * C_OUT];
    __shared__ float ssum[C_OUT], ssq[C_OUT];

    int tid = threadIdx.x;
    for (int i = tid; i < C_HID * C_OUT; i += T5) sw[i] = w3[i];
    if (tid < C_OUT) { ssum[tid] = 0.f; ssq[tid] = 0.f; }

    int row0 = blockIdx.x * ROWS5;
    int nrows = min(ROWS5, N_PTS - row0);

    for (int i = tid; i < nrows * C_HID; i += T5) {
        int r = i / C_HID, cc = i % C_HID;
        float x = g_x2[(row0 + r) * C_HID + cc];
        sx[r][cc] = fminf(fmaxf(x * g_scale2[cc] + g_shift2[cc], 0.f), 6.f);
    }
    __syncthreads();

    int c = tid % C_OUT, rl = tid / C_OUT;   // rl in 0..7
    float s = 0.f, q = 0.f;
    for (int r = rl; r < nrows; r += 8) {
        float acc = 0.f;
#pragma unroll
        for (int k = 0; k < C_HID; k++) acc += sx[r][k] * sw[k * C_OUT + c];
        g_y[(row0 + r) * C_OUT + c] = acc;
        s += acc; q += acc * acc;
    }
    atomicAdd(&ssum[c], s);
    atomicAdd(&ssq[c], q);
    __syncthreads();
    if (tid < C_OUT) {
        atomicAdd(&g_s3[tid], ssum[tid]);
        atomicAdd(&g_q3[tid], ssq[tid]);
    }
}

// ---- K7: out = bn3(y) + feats ----
__global__ void k7_out(const float* __restrict__ feats, float* __restrict__ out) {
    int i = blockIdx.x * blockDim.x + threadIdx.x;
    if (i < N_PTS * C_OUT) {
        int c = i % C_OUT;
        out[i] = g_y[i] * g_scale3[c] + g_shift3[c] + feats[i];
    }
}

extern "C" void kernel_launch(void* const* d_in, const int* in_sizes, int n_in,
                              void* d_out, int out_size) {
    const float* feats = (const float*)d_in[0];
    const float* w1    = (const float*)d_in[1];
    const float* g1    = (const float*)d_in[2];
    const float* b1    = (const float*)d_in[3];
    const float* w2    = (const float*)d_in[4];
    const float* g2    = (const float*)d_in[5];
    const float* b2    = (const float*)d_in[6];
    const float* w3    = (const float*)d_in[7];
    const float* g3    = (const float*)d_in[8];
    const float* b3    = (const float*)d_in[9];
    const int*   in_idx = (const int*)d_in[10];
    // d_in[11] out_idx, d_in[12] off_id: unused (gather form makes them implicit)
    float* out = (float*)d_out;

    float *d_s1, *d_q1, *d_s2, *d_q2, *d_s3, *d_q3;
    float *d_sc1, *d_sh1, *d_sc2, *d_sh2, *d_sc3, *d_sh3;
    cudaGetSymbolAddress((void**)&d_s1, g_s1);
    cudaGetSymbolAddress((void**)&d_q1, g_q1);
    cudaGetSymbolAddress((void**)&d_s2, g_s2);
    cudaGetSymbolAddress((void**)&d_q2, g_q2);
    cudaGetSymbolAddress((void**)&d_s3, g_s3);
    cudaGetSymbolAddress((void**)&d_q3, g_q3);
    cudaGetSymbolAddress((void**)&d_sc1, g_scale1);
    cudaGetSymbolAddress((void**)&d_sh1, g_shift1);
    cudaGetSymbolAddress((void**)&d_sc2, g_scale2);
    cudaGetSymbolAddress((void**)&d_sh2, g_shift2);
    cudaGetSymbolAddress((void**)&d_sc3, g_scale3);
    cudaGetSymbolAddress((void**)&d_sh3, g_shift3);

    k0_zero<<<1, 256>>>();

    int nb1 = (N_PTS + ROWS1 - 1) / ROWS1;
    k1_gemm1<<<nb1, C_HID>>>(feats, w1);
    k_fin<<<1, C_HID>>>(g1, b1, d_s1, d_q1, d_sc1, d_sh1, C_HID);

    int nb3 = (N_PTS + ROWS3 - 1) / ROWS3;
    k3_conv<<<nb3, C_HID>>>(w2, in_idx);
    k_fin<<<1, C_HID>>>(g2, b2, d_s2, d_q2, d_sc2, d_sh2, C_HID);

    int nb5 = (N_PTS + ROWS5 - 1) / ROWS5;
    k5_gemm3<<<nb5, T5>>>(w3);
    k_fin<<<1, C_OUT>>>(g3, b3, d_s3, d_q3, d_sc3, d_sh3, C_OUT);

    int total = N_PTS * C_OUT;
    k7_out<<<(total + 255) / 256, 256>>>(feats, out);
}

// round 2
// speedup vs baseline: 1.1443x; 1.1443x over previous
#include <cuda_runtime.h>
#include <cuda_bf16.h>

#define N_PTS 100000
#define C_IN 24
#define C_HID 144
#define C_OUT 24
#define KS 9
#define EPS 1e-5f

// ---- scratch (device globals: allocation-free rule) ----
__device__ __align__(16) float g_x1[N_PTS * C_HID];   // GEMM1 output (pre-BN)
__device__ __align__(16) float g_x2[N_PTS * C_HID];   // conv output (pre-BN)
__device__ __align__(16) float g_y [N_PTS * C_OUT];   // GEMM3 output (pre-BN)

__device__ float g_s1[C_HID], g_q1[C_HID];
__device__ float g_s2[C_HID], g_q2[C_HID];
__device__ float g_s3[C_OUT], g_q3[C_OUT];
__device__ __align__(16) float g_scale1[C_HID], g_shift1[C_HID];
__device__ __align__(16) float g_scale2[C_HID], g_shift2[C_HID];
__device__ __align__(16) float g_scale3[C_OUT], g_shift3[C_OUT];

__device__ __forceinline__ float relu6f(float x) { return fminf(fmaxf(x, 0.f), 6.f); }

// ---- K0: zero stat accumulators (deterministic graph replays) ----
__global__ void k0_zero() {
    int i = threadIdx.x;
    if (i < C_HID) {
        g_s1[i] = 0.f; g_q1[i] = 0.f;
        g_s2[i] = 0.f; g_q2[i] = 0.f;
    }
    if (i < C_OUT) { g_s3[i] = 0.f; g_q3[i] = 0.f; }
}

// ---- K1: x1 = feats @ w1 (+ per-channel sum/sumsq), 8 rows x 4 cols / thread ----
#define R1 64
#define T1 288
__global__ void __launch_bounds__(T1) k1_gemm1(const float* __restrict__ feats,
                                               const float* __restrict__ w1) {
    __shared__ __align__(16) float sfT[C_IN][R1];        // feats transposed
    __shared__ __align__(16) float sw1[C_IN * C_HID];
    __shared__ __align__(16) float rs[8][C_HID], rq[8][C_HID];

    int tid = threadIdx.x;
    int row0 = blockIdx.x * R1;

    for (int i = tid; i < C_IN * C_HID; i += T1) sw1[i] = w1[i];
    for (int i = tid; i < R1 * C_IN; i += T1) {
        int r = i / C_IN, k = i % C_IN;
        int rr = row0 + r;
        sfT[k][r] = (rr < N_PTS) ? feats[rr * C_IN + k] : 0.f;
    }
    __syncthreads();

    int c4 = tid % 36, rg = tid / 36;      // cols c4*4..+3, rows rg*8..+7
    int cb = c4 * 4;
    float4 acc[8];
#pragma unroll
    for (int j = 0; j < 8; j++) acc[j] = make_float4(0.f, 0.f, 0.f, 0.f);

#pragma unroll
    for (int k = 0; k < C_IN; k++) {
        float4 w  = *(const float4*)&sw1[k * C_HID + cb];
        float4 xa = *(const float4*)&sfT[k][rg * 8];
        float4 xb = *(const float4*)&sfT[k][rg * 8 + 4];
        float xr[8] = {xa.x, xa.y, xa.z, xa.w, xb.x, xb.y, xb.z, xb.w};
#pragma unroll
        for (int j = 0; j < 8; j++) {
            acc[j].x = fmaf(w.x, xr[j], acc[j].x);
            acc[j].y = fmaf(w.y, xr[j], acc[j].y);
            acc[j].z = fmaf(w.z, xr[j], acc[j].z);
            acc[j].w = fmaf(w.w, xr[j], acc[j].w);
        }
    }

    float4 s4 = make_float4(0.f, 0.f, 0.f, 0.f), q4 = s4;
#pragma unroll
    for (int j = 0; j < 8; j++) {
        int rr = row0 + rg * 8 + j;
        if (rr < N_PTS) *(float4*)&g_x1[(size_t)rr * C_HID + cb] = acc[j];
        s4.x += acc[j].x; s4.y += acc[j].y; s4.z += acc[j].z; s4.w += acc[j].w;
        q4.x += acc[j].x * acc[j].x; q4.y += acc[j].y * acc[j].y;
        q4.z += acc[j].z * acc[j].z; q4.w += acc[j].w * acc[j].w;
    }
    *(float4*)&rs[rg][cb] = s4;
    *(float4*)&rq[rg][cb] = q4;
    __syncthreads();
    if (tid < C_HID) {
        float s = 0.f, q = 0.f;
#pragma unroll
        for (int g = 0; g < 8; g++) { s += rs[g][tid]; q += rq[g][tid]; }
        atomicAdd(&g_s1[tid], s);
        atomicAdd(&g_q1[tid], q);
    }
}

// ---- finalize BN: bn(x) = x*scale + shift ----
__global__ void k_fin(const float* __restrict__ g, const float* __restrict__ b,
                      const float* __restrict__ sum, const float* __restrict__ sq,
                      float* __restrict__ scale, float* __restrict__ shift, int C) {
    int c = threadIdx.x;
    if (c < C) {
        float m = sum[c] * (1.0f / N_PTS);
        float v = sq[c] * (1.0f / N_PTS) - m * m;
        float sc = g[c] * rsqrtf(v + EPS);
        scale[c] = sc;
        shift[c] = b[c] - m * sc;
    }
}

// ---- K3: channelwise 3x3 sparse conv (gather) + BN2 stats, float4/thread ----
#define R3 64
#define T3 288
__global__ void __launch_bounds__(T3) k3_conv(const float* __restrict__ w2,
                                              const int* __restrict__ in_idx) {
    __shared__ int snbr[R3][KS];
    __shared__ __align__(16) float rs[8][C_HID], rq[8][C_HID];

    int tid = threadIdx.x;
    int row0 = blockIdx.x * R3;

    for (int i = tid; i < R3 * KS; i += T3) {
        int k = i / R3, r = i % R3;          // coalesced in_idx reads
        int rr = row0 + r;
        snbr[r][k] = (rr < N_PTS) ? in_idx[k * N_PTS + rr] : N_PTS;
    }
    __syncthreads();

    int c4 = tid % 36, rl = tid / 36;
    int cb = c4 * 4;
    float4 wk[KS];
#pragma unroll
    for (int k = 0; k < KS; k++) wk[k] = *(const float4*)&w2[k * C_HID + cb];
    float4 sc = *(const float4*)&g_scale1[cb];
    float4 sh = *(const float4*)&g_shift1[cb];

    float4 s4 = make_float4(0.f, 0.f, 0.f, 0.f), q4 = s4;
#pragma unroll
    for (int j = 0; j < 8; j++) {
        int r = rl * 8 + j;
        float4 acc = make_float4(0.f, 0.f, 0.f, 0.f);
#pragma unroll
        for (int k = 0; k < KS; k++) {
            int nbr = snbr[r][k];
            if (nbr < N_PTS) {
                float4 x = *(const float4*)&g_x1[(size_t)nbr * C_HID + cb];
                float vx = relu6f(fmaf(x.x, sc.x, sh.x));
                float vy = relu6f(fmaf(x.y, sc.y, sh.y));
                float vz = relu6f(fmaf(x.z, sc.z, sh.z));
                float vw = relu6f(fmaf(x.w, sc.w, sh.w));
                acc.x = fmaf(wk[k].x, vx, acc.x);
                acc.y = fmaf(wk[k].y, vy, acc.y);
                acc.z = fmaf(wk[k].z, vz, acc.z);
                acc.w = fmaf(wk[k].w, vw, acc.w);
            }
        }
        int rr = row0 + r;
        if (rr < N_PTS) *(float4*)&g_x2[(size_t)rr * C_HID + cb] = acc;
        s4.x += acc.x; s4.y += acc.y; s4.z += acc.z; s4.w += acc.w;
        q4.x += acc.x * acc.x; q4.y += acc.y * acc.y;
        q4.z += acc.z * acc.z; q4.w += acc.w * acc.w;
    }
    *(float4*)&rs[rl][cb] = s4;
    *(float4*)&rq[rl][cb] = q4;
    __syncthreads();
    if (tid < C_HID) {
        float s = 0.f, q = 0.f;
#pragma unroll
        for (int g = 0; g < 8; g++) { s += rs[g][tid]; q += rq[g][tid]; }
        atomicAdd(&g_s2[tid], s);
        atomicAdd(&g_q2[tid], q);
    }
}

// ---- K5: y = relu6(bn2(x2)) @ w3 + BN3 stats (k-chunked smem) ----
#define R5 64
#define T5 192
#define KC 72
__global__ void __launch_bounds__(T5) k5_gemm3(const float* __restrict__ w3) {
    __shared__ __align__(16) float sxT[KC][R5 + 1];
    __shared__ __align__(16) float sw3[C_HID * C_OUT];
    __shared__ __align__(16) float rs[32][C_OUT], rq[32][C_OUT];

    int tid = threadIdx.x;
    int row0 = blockIdx.x * R5;

    for (int i = tid; i < C_HID * C_OUT; i += T5) sw3[i] = w3[i];

    int c4 = tid % 6, rg = tid / 6;   // cols c4*4..+3, rows rg*2, rg*2+1
    int cb = c4 * 4;
    int r0 = rg * 2;
    float4 acc0 = make_float4(0.f, 0.f, 0.f, 0.f), acc1 = acc0;

    for (int kc = 0; kc < C_HID; kc += KC) {
        __syncthreads();
        for (int i = tid; i < KC * R5; i += T5) {
            int r = i / KC, k = i % KC;          // coalesced g_x2 reads
            int rr = row0 + r;
            float v = 0.f;
            if (rr < N_PTS) {
                int ch = kc + k;
                float x = g_x2[(size_t)rr * C_HID + ch];
                v = relu6f(fmaf(x, g_scale2[ch], g_shift2[ch]));
            }
            sxT[k][r] = v;
        }
        __syncthreads();
#pragma unroll 8
        for (int k = 0; k < KC; k++) {
            float4 w = *(const float4*)&sw3[(kc + k) * C_OUT + cb];
            float x0 = sxT[k][r0];
            float x1 = sxT[k][r0 + 1];
            acc0.x = fmaf(w.x, x0, acc0.x); acc0.y = fmaf(w.y, x0, acc0.y);
            acc0.z = fmaf(w.z, x0, acc0.z); acc0.w = fmaf(w.w, x0, acc0.w);
            acc1.x = fmaf(w.x, x1, acc1.x); acc1.y = fmaf(w.y, x1, acc1.y);
            acc1.z = fmaf(w.z, x1, acc1.z); acc1.w = fmaf(w.w, x1, acc1.w);
        }
    }

    int rr0 = row0 + r0;
    if (rr0 < N_PTS)     *(float4*)&g_y[(size_t)rr0 * C_OUT + cb] = acc0;
    if (rr0 + 1 < N_PTS) *(float4*)&g_y[(size_t)(rr0 + 1) * C_OUT + cb] = acc1;

    float4 s4, q4;
    s4.x = acc0.x + acc1.x; s4.y = acc0.y + acc1.y;
    s4.z = acc0.z + acc1.z; s4.w = acc0.w + acc1.w;
    q4.x = acc0.x * acc0.x + acc1.x * acc1.x;
    q4.y = acc0.y * acc0.y + acc1.y * acc1.y;
    q4.z = acc0.z * acc0.z + acc1.z * acc1.z;
    q4.w = acc0.w * acc0.w + acc1.w * acc1.w;
    *(float4*)&rs[rg][cb] = s4;
    *(float4*)&rq[rg][cb] = q4;
    __syncthreads();
    if (tid < C_OUT) {
        float s = 0.f, q = 0.f;
#pragma unroll
        for (int g = 0; g < 32; g++) { s += rs[g][tid]; q += rq[g][tid]; }
        atomicAdd(&g_s3[tid], s);
        atomicAdd(&g_q3[tid], q);
    }
}

// ---- K7: out = bn3(y) + feats (float4) ----
__global__ void k7_out(const float* __restrict__ feats, float* __restrict__ out) {
    int i = blockIdx.x * blockDim.x + threadIdx.x;   // float4 index
    if (i < N_PTS * C_OUT / 4) {
        int cb = (i % 6) * 4;
        float4 y  = *(const float4*)&g_y[i * 4];
        float4 f  = *(const float4*)&feats[i * 4];
        float4 sc = *(const float4*)&g_scale3[cb];
        float4 sh = *(const float4*)&g_shift3[cb];
        float4 o;
        o.x = fmaf(y.x, sc.x, sh.x) + f.x;
        o.y = fmaf(y.y, sc.y, sh.y) + f.y;
        o.z = fmaf(y.z, sc.z, sh.z) + f.z;
        o.w = fmaf(y.w, sc.w, sh.w) + f.w;
        *(float4*)&out[i * 4] = o;
    }
}

extern "C" void kernel_launch(void* const* d_in, const int* in_sizes, int n_in,
                              void* d_out, int out_size) {
    const float* feats = (const float*)d_in[0];
    const float* w1    = (const float*)d_in[1];
    const float* g1    = (const float*)d_in[2];
    const float* b1    = (const float*)d_in[3];
    const float* w2    = (const float*)d_in[4];
    const float* g2    = (const float*)d_in[5];
    const float* b2    = (const float*)d_in[6];
    const float* w3    = (const float*)d_in[7];
    const float* g3    = (const float*)d_in[8];
    const float* b3    = (const float*)d_in[9];
    const int*   in_idx = (const int*)d_in[10];
    float* out = (float*)d_out;

    float *d_s1, *d_q1, *d_s2, *d_q2, *d_s3, *d_q3;
    float *d_sc1, *d_sh1, *d_sc2, *d_sh2, *d_sc3, *d_sh3;
    cudaGetSymbolAddress((void**)&d_s1, g_s1);
    cudaGetSymbolAddress((void**)&d_q1, g_q1);
    cudaGetSymbolAddress((void**)&d_s2, g_s2);
    cudaGetSymbolAddress((void**)&d_q2, g_q2);
    cudaGetSymbolAddress((void**)&d_s3, g_s3);
    cudaGetSymbolAddress((void**)&d_q3, g_q3);
    cudaGetSymbolAddress((void**)&d_sc1, g_scale1);
    cudaGetSymbolAddress((void**)&d_sh1, g_shift1);
    cudaGetSymbolAddress((void**)&d_sc2, g_scale2);
    cudaGetSymbolAddress((void**)&d_sh2, g_shift2);
    cudaGetSymbolAddress((void**)&d_sc3, g_scale3);
    cudaGetSymbolAddress((void**)&d_sh3, g_shift3);

    k0_zero<<<1, 256>>>();

    int nb1 = (N_PTS + R1 - 1) / R1;
    k1_gemm1<<<nb1, T1>>>(feats, w1);
    k_fin<<<1, C_HID>>>(g1, b1, d_s1, d_q1, d_sc1, d_sh1, C_HID);

    int nb3 = (N_PTS + R3 - 1) / R3;
    k3_conv<<<nb3, T3>>>(w2, in_idx);
    k_fin<<<1, C_HID>>>(g2, b2, d_s2, d_q2, d_sc2, d_sh2, C_HID);

    int nb5 = (N_PTS + R5 - 1) / R5;
    k5_gemm3<<<nb5, T5>>>(w3);
    k_fin<<<1, C_OUT>>>(g3, b3, d_s3, d_q3, d_sc3, d_sh3, C_OUT);

    int total4 = N_PTS * C_OUT / 4;
    k7_out<<<(total4 + 255) / 256, 256>>>(feats, out);
}

// round 3
// speedup vs baseline: 1.3049x; 1.1404x over previous
#include <cuda_runtime.h>
#include <cuda_bf16.h>

#define N_PTS 100000
#define C_IN 24
#define C_HID 144
#define C_OUT 24
#define KS 9
#define EPS 1e-5f

// ---- scratch (device globals: allocation-free rule) ----
// g_x1 has one extra sentinel row (index N_PTS) that maps to 0 after bn1+relu6.
__device__ __align__(16) float g_x1[(N_PTS + 1) * C_HID];
__device__ __align__(16) float g_x2[N_PTS * C_HID];
__device__ __align__(16) float g_y [N_PTS * C_OUT];

__device__ float g_s1[C_HID], g_q1[C_HID];
__device__ float g_s2[C_HID], g_q2[C_HID];
__device__ float g_s3[C_OUT], g_q3[C_OUT];
__device__ __align__(16) float g_scale1[C_HID], g_shift1[C_HID];
__device__ __align__(16) float g_scale2[C_HID], g_shift2[C_HID];
__device__ __align__(16) float g_scale3[C_OUT], g_shift3[C_OUT];

__device__ __forceinline__ float relu6f(float x) { return fminf(fmaxf(x, 0.f), 6.f); }

// ---- K1: x1 = feats @ w1 (+ per-channel sum/sumsq), 8 rows x 4 cols / thread ----
#define R1 64
#define T1 288
__global__ void __launch_bounds__(T1) k1_gemm1(const float* __restrict__ feats,
                                               const float* __restrict__ w1) {
    __shared__ __align__(16) float sfT[C_IN][R1];
    __shared__ __align__(16) float sw1[C_IN * C_HID];
    __shared__ __align__(16) float rs[8][C_HID], rq[8][C_HID];

    int tid = threadIdx.x;
    int row0 = blockIdx.x * R1;

    for (int i = tid; i < C_IN * C_HID; i += T1) sw1[i] = w1[i];
    for (int i = tid; i < R1 * C_IN; i += T1) {
        int r = i / C_IN, k = i % C_IN;
        int rr = row0 + r;
        sfT[k][r] = (rr < N_PTS) ? feats[rr * C_IN + k] : 0.f;
    }
    __syncthreads();

    int c4 = tid % 36, rg = tid / 36;
    int cb = c4 * 4;
    float4 acc[8];
#pragma unroll
    for (int j = 0; j < 8; j++) acc[j] = make_float4(0.f, 0.f, 0.f, 0.f);

#pragma unroll
    for (int k = 0; k < C_IN; k++) {
        float4 w  = *(const float4*)&sw1[k * C_HID + cb];
        float4 xa = *(const float4*)&sfT[k][rg * 8];
        float4 xb = *(const float4*)&sfT[k][rg * 8 + 4];
        float xr[8] = {xa.x, xa.y, xa.z, xa.w, xb.x, xb.y, xb.z, xb.w};
#pragma unroll
        for (int j = 0; j < 8; j++) {
            acc[j].x = fmaf(w.x, xr[j], acc[j].x);
            acc[j].y = fmaf(w.y, xr[j], acc[j].y);
            acc[j].z = fmaf(w.z, xr[j], acc[j].z);
            acc[j].w = fmaf(w.w, xr[j], acc[j].w);
        }
    }

    float4 s4 = make_float4(0.f, 0.f, 0.f, 0.f), q4 = s4;
#pragma unroll
    for (int j = 0; j < 8; j++) {
        int rr = row0 + rg * 8 + j;
        if (rr < N_PTS) *(float4*)&g_x1[(size_t)rr * C_HID + cb] = acc[j];
        s4.x += acc[j].x; s4.y += acc[j].y; s4.z += acc[j].z; s4.w += acc[j].w;
        q4.x += acc[j].x * acc[j].x; q4.y += acc[j].y * acc[j].y;
        q4.z += acc[j].z * acc[j].z; q4.w += acc[j].w * acc[j].w;
    }
    *(float4*)&rs[rg][cb] = s4;
    *(float4*)&rq[rg][cb] = q4;
    __syncthreads();
    if (tid < C_HID) {
        float s = 0.f, q = 0.f;
#pragma unroll
        for (int g = 0; g < 8; g++) { s += rs[g][tid]; q += rq[g][tid]; }
        atomicAdd(&g_s1[tid], s);
        atomicAdd(&g_q1[tid], q);
    }
}

// ---- finalize BN; optionally write sentinel row; zero next stage's accumulators ----
__global__ void k_fin(const float* __restrict__ g, const float* __restrict__ b,
                      const float* __restrict__ sum, const float* __restrict__ sq,
                      float* __restrict__ scale, float* __restrict__ shift, int C,
                      float* __restrict__ sentinel,      // nullable
                      float* __restrict__ zs, float* __restrict__ zq, int ZC) {
    int c = threadIdx.x;
    if (c < C) {
        float m = sum[c] * (1.0f / N_PTS);
        float v = sq[c] * (1.0f / N_PTS) - m * m;
        float sc = g[c] * rsqrtf(v + EPS);
        float sh = b[c] - m * sc;
        scale[c] = sc;
        shift[c] = sh;
        if (sentinel) sentinel[c] = (sc != 0.f) ? (-sh / sc) : 0.f;
    }
    if (zs && c < ZC) { zs[c] = 0.f; zq[c] = 0.f; }
}

// ---- K3: channelwise 3x3 sparse conv (gather) + BN2 stats ----
// Branchless: sentinel row of g_x1 maps to 0 after bn1+relu6. float2/thread.
#define R3 32
#define T3 288   // 72 channel-groups (float2) x 4 row-lanes; R3*KS == 288
__global__ void __launch_bounds__(T3) k3_conv(const float* __restrict__ w2,
                                              const int* __restrict__ in_idx) {
    __shared__ int snbr[R3][KS];
    __shared__ __align__(8) float rs[4][C_HID], rq[4][C_HID];

    int tid = threadIdx.x;
    int row0 = blockIdx.x * R3;      // N_PTS % R3 == 0: no guards

    {   // one coalesced in_idx load per thread (in_idx layout: [KS][N])
        int k = tid / R3, r = tid % R3;
        snbr[r][k] = in_idx[k * N_PTS + row0 + r];
    }
    __syncthreads();

    int cg = tid % 72, rl = tid / 72;     // channels 2cg..2cg+1, row-lane rl
    int cb = cg * 2;

    float2 wk[KS];
#pragma unroll
    for (int k = 0; k < KS; k++) wk[k] = *(const float2*)&w2[k * C_HID + cb];
    float2 sc = *(const float2*)&g_scale1[cb];
    float2 sh = *(const float2*)&g_shift1[cb];

    float s0 = 0.f, s1 = 0.f, q0 = 0.f, q1 = 0.f;
#pragma unroll 1
    for (int j = 0; j < 8; j++) {
        int r = rl * 8 + j;
        float2 lx[KS];
#pragma unroll
        for (int k = 0; k < KS; k++) {
            int nbr = snbr[r][k];         // sentinel = N_PTS (valid row)
            lx[k] = *(const float2*)&g_x1[(size_t)nbr * C_HID + cb];
        }
        float a0 = 0.f, a1 = 0.f;
#pragma unroll
        for (int k = 0; k < KS; k++) {
            float v0 = relu6f(fmaf(lx[k].x, sc.x, sh.x));
            float v1 = relu6f(fmaf(lx[k].y, sc.y, sh.y));
            a0 = fmaf(wk[k].x, v0, a0);
            a1 = fmaf(wk[k].y, v1, a1);
        }
        *(float2*)&g_x2[(size_t)(row0 + r) * C_HID + cb] = make_float2(a0, a1);
        s0 += a0; q0 += a0 * a0;
        s1 += a1; q1 += a1 * a1;
    }
    rs[rl][cb] = s0; rs[rl][cb + 1] = s1;
    rq[rl][cb] = q0; rq[rl][cb + 1] = q1;
    __syncthreads();
    if (tid < C_HID) {
        float s = rs[0][tid] + rs[1][tid] + rs[2][tid] + rs[3][tid];
        float q = rq[0][tid] + rq[1][tid] + rq[2][tid] + rq[3][tid];
        atomicAdd(&g_s2[tid], s);
        atomicAdd(&g_q2[tid], q);
    }
}

// ---- K5: y = relu6(bn2(x2)) @ w3 + BN3 stats (k-chunked smem) ----
#define R5 64
#define T5 192
#define KC 72
__global__ void __launch_bounds__(T5) k5_gemm3(const float* __restrict__ w3) {
    __shared__ __align__(16) float sxT[KC][R5 + 1];
    __shared__ __align__(16) float sw3[C_HID * C_OUT];
    __shared__ __align__(16) float rs[32][C_OUT], rq[32][C_OUT];

    int tid = threadIdx.x;
    int row0 = blockIdx.x * R5;

    for (int i = tid; i < C_HID * C_OUT; i += T5) sw3[i] = w3[i];

    int c4 = tid % 6, rg = tid / 6;
    int cb = c4 * 4;
    int r0 = rg * 2;
    float4 acc0 = make_float4(0.f, 0.f, 0.f, 0.f), acc1 = acc0;

    for (int kc = 0; kc < C_HID; kc += KC) {
        __syncthreads();
        for (int i = tid; i < KC * R5; i += T5) {
            int r = i / KC, k = i % KC;
            int rr = row0 + r;
            float v = 0.f;
            if (rr < N_PTS) {
                int ch = kc + k;
                float x = g_x2[(size_t)rr * C_HID + ch];
                v = relu6f(fmaf(x, g_scale2[ch], g_shift2[ch]));
            }
            sxT[k][r] = v;
        }
        __syncthreads();
#pragma unroll 8
        for (int k = 0; k < KC; k++) {
            float4 w = *(const float4*)&sw3[(kc + k) * C_OUT + cb];
            float x0 = sxT[k][r0];
            float x1 = sxT[k][r0 + 1];
            acc0.x = fmaf(w.x, x0, acc0.x); acc0.y = fmaf(w.y, x0, acc0.y);
            acc0.z = fmaf(w.z, x0, acc0.z); acc0.w = fmaf(w.w, x0, acc0.w);
            acc1.x = fmaf(w.x, x1, acc1.x); acc1.y = fmaf(w.y, x1, acc1.y);
            acc1.z = fmaf(w.z, x1, acc1.z); acc1.w = fmaf(w.w, x1, acc1.w);
        }
    }

    int rr0 = row0 + r0;
    if (rr0 < N_PTS)     *(float4*)&g_y[(size_t)rr0 * C_OUT + cb] = acc0;
    if (rr0 + 1 < N_PTS) *(float4*)&g_y[(size_t)(rr0 + 1) * C_OUT + cb] = acc1;

    float4 s4, q4;
    s4.x = acc0.x + acc1.x; s4.y = acc0.y + acc1.y;
    s4.z = acc0.z + acc1.z; s4.w = acc0.w + acc1.w;
    q4.x = acc0.x * acc0.x + acc1.x * acc1.x;
    q4.y = acc0.y * acc0.y + acc1.y * acc1.y;
    q4.z = acc0.z * acc0.z + acc1.z * acc1.z;
    q4.w = acc0.w * acc0.w + acc1.w * acc1.w;
    *(float4*)&rs[rg][cb] = s4;
    *(float4*)&rq[rg][cb] = q4;
    __syncthreads();
    if (tid < C_OUT) {
        float s = 0.f, q = 0.f;
#pragma unroll
        for (int g = 0; g < 32; g++) { s += rs[g][tid]; q += rq[g][tid]; }
        atomicAdd(&g_s3[tid], s);
        atomicAdd(&g_q3[tid], q);
    }
}

// ---- K7: out = bn3(y) + feats (float4); block 0 re-zeroes stage-1 accumulators ----
__global__ void k7_out(const float* __restrict__ feats, float* __restrict__ out) {
    if (blockIdx.x == 0 && threadIdx.x < C_HID) {
        g_s1[threadIdx.x] = 0.f;
        g_q1[threadIdx.x] = 0.f;
    }
    int i = blockIdx.x * blockDim.x + threadIdx.x;
    if (i < N_PTS * C_OUT / 4) {
        int cb = (i % 6) * 4;
        float4 y  = *(const float4*)&g_y[i * 4];
        float4 f  = *(const float4*)&feats[i * 4];
        float4 sc = *(const float4*)&g_scale3[cb];
        float4 sh = *(const float4*)&g_shift3[cb];
        float4 o;
        o.x = fmaf(y.x, sc.x, sh.x) + f.x;
        o.y = fmaf(y.y, sc.y, sh.y) + f.y;
        o.z = fmaf(y.z, sc.z, sh.z) + f.z;
        o.w = fmaf(y.w, sc.w, sh.w) + f.w;
        *(float4*)&out[i * 4] = o;
    }
}

extern "C" void kernel_launch(void* const* d_in, const int* in_sizes, int n_in,
                              void* d_out, int out_size) {
    const float* feats = (const float*)d_in[0];
    const float* w1    = (const float*)d_in[1];
    const float* g1    = (const float*)d_in[2];
    const float* b1    = (const float*)d_in[3];
    const float* w2    = (const float*)d_in[4];
    const float* g2    = (const float*)d_in[5];
    const float* b2    = (const float*)d_in[6];
    const float* w3    = (const float*)d_in[7];
    const float* g3    = (const float*)d_in[8];
    const float* b3    = (const float*)d_in[9];
    const int*   in_idx = (const int*)d_in[10];
    float* out = (float*)d_out;

    float *d_s1, *d_q1, *d_s2, *d_q2, *d_s3, *d_q3;
    float *d_sc1, *d_sh1, *d_sc2, *d_sh2, *d_sc3, *d_sh3, *d_x1;
    cudaGetSymbolAddress((void**)&d_s1, g_s1);
    cudaGetSymbolAddress((void**)&d_q1, g_q1);
    cudaGetSymbolAddress((void**)&d_s2, g_s2);
    cudaGetSymbolAddress((void**)&d_q2, g_q2);
    cudaGetSymbolAddress((void**)&d_s3, g_s3);
    cudaGetSymbolAddress((void**)&d_q3, g_q3);
    cudaGetSymbolAddress((void**)&d_sc1, g_scale1);
    cudaGetSymbolAddress((void**)&d_sh1, g_shift1);
    cudaGetSymbolAddress((void**)&d_sc2, g_scale2);
    cudaGetSymbolAddress((void**)&d_sh2, g_shift2);
    cudaGetSymbolAddress((void**)&d_sc3, g_scale3);
    cudaGetSymbolAddress((void**)&d_sh3, g_shift3);
    cudaGetSymbolAddress((void**)&d_x1, g_x1);
    float* sentinel1 = d_x1 + (size_t)N_PTS * C_HID;

    int nb1 = (N_PTS + R1 - 1) / R1;
    k1_gemm1<<<nb1, T1>>>(feats, w1);
    k_fin<<<1, C_HID>>>(g1, b1, d_s1, d_q1, d_sc1, d_sh1, C_HID,
                        sentinel1, d_s2, d_q2, C_HID);

    int nb3 = N_PTS / R3;   // exact
    k3_conv<<<nb3, T3>>>(w2, in_idx);
    k_fin<<<1, C_HID>>>(g2, b2, d_s2, d_q2, d_sc2, d_sh2, C_HID,
                        nullptr, d_s3, d_q3, C_OUT);

    int nb5 = (N_PTS + R5 - 1) / R5;
    k5_gemm3<<<nb5, T5>>>(w3);
    k_fin<<<1, C_OUT>>>(g3, b3, d_s3, d_q3, d_sc3, d_sh3, C_OUT,
                        nullptr, nullptr, nullptr, 0);

    int total4 = N_PTS * C_OUT / 4;
    k7_out<<<(total4 + 255) / 256, 256>>>(feats, out);
}